// round 17
// baseline (speedup 1.0000x reference)
#include <cuda_runtime.h>

#define GH 64
#define GW 64
#define NOBJ 16
#define FEAT 256
#define BATCH 4
#define DECAY 0.95f

#define NROWS (BATCH * GH * GW * NOBJ)   // 262144
#define ROW_OUT (FEAT + 2)               // 258 floats = 1032 B

// Same algorithm as R15 (warp = 2 rows = 2064 B span, 129 dense aligned
// STG.128.CS, shuffle realign). Only change: 128-thread CTAs (16/SM) for
// finer load/store phase interleave and smaller scheduling quantum.
__global__ __launch_bounds__(128, 16)
void smg_kernel(const float* __restrict__ grid_state,
                const float* __restrict__ grid_conf,
                const float* __restrict__ grid_temp,
                const float* __restrict__ obj_feat,
                const float* __restrict__ positions,
                const float* __restrict__ occl,
                float* __restrict__ out)
{
    const int lane  = threadIdx.x & 31;
    const int wglob = blockIdx.x * 4 + (threadIdx.x >> 5);
    const int r0    = wglob * 2;                 // even row
    const int cell  = r0 >> 4;
    const int gw    = cell & (GW - 1);
    const int gh    = (cell >> 6) & (GH - 1);
    const int b     = cell >> 12;
    const int bo0   = b * NOBJ + (r0 & (NOBJ - 1));
    const int bo1   = bo0 + 1;

    // ---- Warp-uniform scalar loads (default policy: tiny reused tables) ----
    const float px0 = positions[2 * bo0], py0 = positions[2 * bo0 + 1];
    const float px1 = positions[2 * bo1], py1 = positions[2 * bo1 + 1];
    const float oc0 = occl[bo0],          oc1 = occl[bo1];

    // ---- Front-batched bulk loads: 4x LDG.128.CS ----
    const float4* gs = (const float4*)grid_state + (size_t)r0 * (FEAT / 4);
    float4 v[4];
    #pragma unroll
    for (int j = 0; j < 4; j++)
        v[j] = __ldcs(&gs[lane + 32 * j]);

    // ---- Predicate + alpha (uniform in all lanes) ----
    const int gwt0 = (int)fminf(fmaxf(px0 * (float)(GW - 1), 0.0f), 63.0f);
    const int ght0 = (int)fminf(fmaxf(py0 * (float)(GH - 1), 0.0f), 63.0f);
    const int gwt1 = (int)fminf(fmaxf(px1 * (float)(GW - 1), 0.0f), 63.0f);
    const int ght1 = (int)fminf(fmaxf(py1 * (float)(GH - 1), 0.0f), 63.0f);
    const bool vis0 = oc0 < 0.5f, vis1 = oc1 < 0.5f;
    const float a0 = ((gwt0 == gw) && (ght0 == gh)) ? (vis0 ? 0.8f : 0.3f) : 0.0f;
    const float a1 = ((gwt1 == gw) && (ght1 == gh)) ? (vis1 ? 0.8f : 0.3f) : 0.0f;

    // ---- Lane 0: conf/temp for both rows ----
    float c0d = 0.0f, t0f = 0.0f, c1d = 0.0f, t1f = 0.0f;
    if (lane == 0) {
        const float2 c2 = *(const float2*)(grid_conf + r0);
        const float2 t2 = *(const float2*)(grid_temp + r0);
        float c0 = c2.x, t0 = t2.x, c1 = c2.y, t1 = t2.y;
        if (a0 != 0.0f) {
            c0 = vis0 ? fminf(1.0f, c0 * 0.9f + 0.5f) : c0 * DECAY;
            t0 += vis0 ? 1.0f : 0.5f;
        }
        if (a1 != 0.0f) {
            c1 = vis1 ? fminf(1.0f, c1 * 0.9f + 0.5f) : c1 * DECAY;
            t1 += vis1 ? 1.0f : 0.5f;
        }
        c0d = c0 * DECAY; t0f = t0;
        c1d = c1 * DECAY; t1f = t1;
    }

    // ---- Feature blend (warp-uniform; taken by 64 of 131072 warps) ----
    if (a0 != 0.0f) {
        const float4* of = (const float4*)(obj_feat + (size_t)bo0 * FEAT);
        const float ia = 1.0f - a0;
        float4 f;
        f = of[lane];
        v[0].x = a0 * f.x + ia * v[0].x;  v[0].y = a0 * f.y + ia * v[0].y;
        v[0].z = a0 * f.z + ia * v[0].z;  v[0].w = a0 * f.w + ia * v[0].w;
        f = of[lane + 32];
        v[1].x = a0 * f.x + ia * v[1].x;  v[1].y = a0 * f.y + ia * v[1].y;
        v[1].z = a0 * f.z + ia * v[1].z;  v[1].w = a0 * f.w + ia * v[1].w;
    }
    if (a1 != 0.0f) {
        const float4* of = (const float4*)(obj_feat + (size_t)bo1 * FEAT);
        const float ia = 1.0f - a1;
        float4 f;
        f = of[lane];
        v[2].x = a1 * f.x + ia * v[2].x;  v[2].y = a1 * f.y + ia * v[2].y;
        v[2].z = a1 * f.z + ia * v[2].z;  v[2].w = a1 * f.w + ia * v[2].w;
        f = of[lane + 32];
        v[3].x = a1 * f.x + ia * v[3].x;  v[3].y = a1 * f.y + ia * v[3].y;
        v[3].z = a1 * f.z + ia * v[3].z;  v[3].w = a1 * f.w + ia * v[3].w;
    }

    // ---- Realign row1 by 2 floats via lane shuffles ----
    const unsigned FM = 0xffffffffu;
    const int nxt = (lane + 1) & 31;
    const float sAx = (lane == 0) ? v[3].x : v[2].x;
    const float sAy = (lane == 0) ? v[3].y : v[2].y;
    const float sBx = (lane == 0) ? c1d     : v[3].x;
    const float sBy = (lane == 0) ? t1f     : v[3].y;
    const float xA = __shfl_sync(FM, sAx, nxt);
    const float yA = __shfl_sync(FM, sAy, nxt);
    const float xB = __shfl_sync(FM, sBx, nxt);
    const float yB = __shfl_sync(FM, sBy, nxt);

    // ---- Stores: 129 dense aligned STG.128.CS across the 2064 B span ----
    float4* base = (float4*)(out + (size_t)r0 * ROW_OUT);
    __stcs(&base[lane],      v[0]);
    __stcs(&base[lane + 32], v[1]);
    if (lane == 0)
        __stcs(&base[64], make_float4(c0d, t0f, v[2].x, v[2].y));
    __stcs(&base[65 + lane], make_float4(v[2].z, v[2].w, xA, yA));
    __stcs(&base[97 + lane], make_float4(v[3].z, v[3].w, xB, yB));
}

extern "C" void kernel_launch(void* const* d_in, const int* in_sizes, int n_in,
                              void* d_out, int out_size)
{
    const float* grid_state = (const float*)d_in[0];
    const float* grid_conf  = (const float*)d_in[1];
    const float* grid_temp  = (const float*)d_in[2];
    const float* obj_feat   = (const float*)d_in[3];
    const float* positions  = (const float*)d_in[4];
    const float* occl       = (const float*)d_in[5];
    float* out = (float*)d_out;

    smg_kernel<<<NROWS / 8, 128>>>(grid_state, grid_conf, grid_temp,
                                   obj_feat, positions, occl, out);
}